// round 14
// baseline (speedup 1.0000x reference)
#include <cuda_runtime.h>
#include <cuda_fp16.h>
#include <cstdint>
#include <cstring>
#include <math.h>

#define BSZ   16
#define TSEQ  2048
#define DIM   1024
#define MDIM  128
#define HID   512
#define WIN   16
#define HALF  8
#define MAXP  6
#define NW    128
#define PPAIR 768
#define KSEL  614
#define TKEEP 1434
#define NTOK  (BSZ*TSEQ)
#define NCOL  640
#define LN_EPS 1e-5f

#define KC          32               // K chunk
#define NKCHUNK     (DIM/KC)         // 32
#define NSTAGE      4
#define SSTRIDE     40               // padded half stride per row (32 used)
#define TILE_H      (128*SSTRIDE)    // halves per plane (5120)
#define TILE_B      (TILE_H*2)       // 10240 bytes
#define STAGE_B     (4*TILE_B)       // Ah, Al, Bh, Bl = 40960 bytes
#define GEMM_SMEM   (NSTAGE*STAGE_B) // 163840 bytes
#define FSTRIDE     132              // fp32 epilogue tile stride

// ---------------- scratch ---------------------------------------------------
__device__ __half g_Ah[(size_t)NTOK*DIM];
__device__ __half g_Al[(size_t)NTOK*DIM];     // TRUE-scale lo residual
__device__ __half g_Wh[NCOL*DIM];             // folded weights hi, [n][k]
__device__ __half g_Wl[NCOL*DIM];             // TRUE-scale lo residual, [n][k]
__device__ float g_cvec[NCOL];
__device__ float g_mnorm[(size_t)NTOK*MDIM];
__device__ float g_impPart[4*NTOK];
__device__ int   g_pi[BSZ*PPAIR];
__device__ int   g_pj[BSZ*PPAIR];
__device__ float g_ps[BSZ*PPAIR];
__device__ float g_pal[BSZ*PPAIR];
__device__ int   g_inv[BSZ*TKEEP];
__device__ int   g_partner[BSZ*TSEQ];
__device__ float g_atok[BSZ*TSEQ];

// ---------------- helpers ---------------------------------------------------
__device__ __forceinline__ float block_reduce_sum(float v, float* sbuf) {
    int lane = threadIdx.x & 31, wid = threadIdx.x >> 5;
    #pragma unroll
    for (int o = 16; o; o >>= 1) v += __shfl_xor_sync(0xffffffffu, v, o);
    if (lane == 0) sbuf[wid] = v;
    __syncthreads();
    int nw = blockDim.x >> 5;
    float r = (threadIdx.x < nw) ? sbuf[threadIdx.x] : 0.f;
    if (wid == 0) {
        #pragma unroll
        for (int o = 16; o; o >>= 1) r += __shfl_xor_sync(0xffffffffu, r, o);
        if (lane == 0) sbuf[0] = r;
    }
    __syncthreads();
    r = sbuf[0];
    __syncthreads();
    return r;
}

__device__ __forceinline__ float warp_sum(float v) {
    #pragma unroll
    for (int o = 16; o; o >>= 1) v += __shfl_xor_sync(0xffffffffu, v, o);
    return v;
}

__device__ __forceinline__ void mma16816(float c[4], const unsigned a[4], const unsigned b[2]) {
    asm volatile("mma.sync.aligned.m16n8k16.row.col.f32.f16.f16.f32 "
        "{%0,%1,%2,%3}, {%4,%5,%6,%7}, {%8,%9}, {%0,%1,%2,%3};"
        : "+f"(c[0]), "+f"(c[1]), "+f"(c[2]), "+f"(c[3])
        : "r"(a[0]), "r"(a[1]), "r"(a[2]), "r"(a[3]), "r"(b[0]), "r"(b[1]));
}

__device__ __forceinline__ void ldsm_x4(unsigned r[4], unsigned addr) {
    asm volatile("ldmatrix.sync.aligned.m8n8.x4.shared.b16 {%0,%1,%2,%3}, [%4];"
        : "=r"(r[0]), "=r"(r[1]), "=r"(r[2]), "=r"(r[3]) : "r"(addr));
}

__device__ __forceinline__ unsigned smem_u32(const void* p) {
    unsigned a;
    asm("{ .reg .u64 t; cvta.to.shared.u64 t, %1; cvt.u32.u64 %0, t; }" : "=r"(a) : "l"(p));
    return a;
}

__device__ __forceinline__ void cp16(unsigned dst, const void* src) {
    asm volatile("cp.async.cg.shared.global [%0], [%1], 16;" :: "r"(dst), "l"(src));
}
#define CP_COMMIT() asm volatile("cp.async.commit_group;" ::: "memory")
#define CP_WAIT(N)  asm volatile("cp.async.wait_group %0;" :: "n"(N) : "memory")

__device__ __forceinline__ unsigned pack_h2(__half a, __half b) {
    __half2 h = __halves2half2(a, b);
    unsigned u; memcpy(&u, &h, 4); return u;
}

// ---------------- K0: LN + split (true-scale lo) ----------------------------
__global__ void ln_split_kernel(const float* __restrict__ x) {
    int t = blockIdx.x * 8 + (threadIdx.x >> 5);
    int lane = threadIdx.x & 31;
    const float4* row = (const float4*)(x + (size_t)t * DIM);
    float4 v[8];
    float s = 0.f;
    #pragma unroll
    for (int j = 0; j < 8; j++) {
        v[j] = row[lane + 32*j];
        s += v[j].x + v[j].y + v[j].z + v[j].w;
    }
    float mean = warp_sum(s) * (1.0f / DIM);
    float ss = 0.f;
    #pragma unroll
    for (int j = 0; j < 8; j++) {
        float d0 = v[j].x-mean, d1 = v[j].y-mean, d2 = v[j].z-mean, d3 = v[j].w-mean;
        ss += d0*d0 + d1*d1 + d2*d2 + d3*d3;
    }
    float rs = rsqrtf(warp_sum(ss) * (1.0f / DIM) + LN_EPS);
    #pragma unroll
    for (int j = 0; j < 8; j++) {
        float f[4] = {(v[j].x-mean)*rs, (v[j].y-mean)*rs, (v[j].z-mean)*rs, (v[j].w-mean)*rs};
        unsigned hp[2], lp[2];
        #pragma unroll
        for (int e = 0; e < 2; e++) {
            __half h0 = __float2half_rn(f[2*e]),   h1 = __float2half_rn(f[2*e+1]);
            __half l0 = __float2half_rn(f[2*e]   - __half2float(h0));
            __half l1 = __float2half_rn(f[2*e+1] - __half2float(h1));
            hp[e] = pack_h2(h0, h1);  lp[e] = pack_h2(l0, l1);
        }
        size_t off = (size_t)t * DIM + (lane + 32*j) * 4;
        *(uint2*)(g_Ah + off) = make_uint2(hp[0], hp[1]);
        *(uint2*)(g_Al + off) = make_uint2(lp[0], lp[1]);
    }
}

// ---------------- fold weights into split fp16 [n][k] -----------------------
__global__ void foldW_kernel(const float* __restrict__ wm, const float* __restrict__ w1,
                             const float* __restrict__ gm, const float* __restrict__ gi) {
    __shared__ float tile[32][33];
    int k0 = blockIdx.x * 32, n0 = blockIdx.y * 32;
    int tx = threadIdx.x, ty = threadIdx.y;
    #pragma unroll
    for (int j = 0; j < 4; j++) {
        int k = k0 + ty + j*8, n = n0 + tx;
        float w = (n < MDIM) ? gm[k] * wm[k*MDIM + n]
                             : gi[k] * w1[k*HID + (n - MDIM)];
        tile[ty + j*8][tx] = w;
    }
    __syncthreads();
    #pragma unroll
    for (int j = 0; j < 4; j++) {
        int n = n0 + ty + j*8, k = k0 + tx;
        float w = tile[tx][ty + j*8];
        __half h = __float2half_rn(w);
        g_Wh[(size_t)n*DIM + k] = h;
        g_Wl[(size_t)n*DIM + k] = __float2half_rn(w - __half2float(h));
    }
}

__global__ void foldC_kernel(const float* __restrict__ wm, const float* __restrict__ w1,
                             const float* __restrict__ bm, const float* __restrict__ bi,
                             const float* __restrict__ b1) {
    int n = blockIdx.x;
    __shared__ float sbuf[32];
    float s = 0.f;
    if (n < MDIM) {
        for (int d = threadIdx.x; d < DIM; d += blockDim.x) s += bm[d] * wm[d*MDIM + n];
    } else {
        for (int d = threadIdx.x; d < DIM; d += blockDim.x) s += bi[d] * w1[d*HID + (n - MDIM)];
    }
    float tot = block_reduce_sum(s, sbuf);
    if (threadIdx.x == 0) g_cvec[n] = tot + ((n >= MDIM) ? b1[n - MDIM] : 0.f);
}

// ---------------- K1: split-fp16 HMMA GEMM, single-acc, dbl-buffered frags --
// grid (5, 256): bn = 128*bx, bm = 128*by.  512 threads = 4x4 warps, 32x32/warp.
#define LDFRAG(AH, AL, BH, BL, kb) do {                                           \
    _Pragma("unroll")                                                             \
    for (int _ma = 0; _ma < 2; _ma++) {                                           \
        unsigned _adr = stA + (unsigned)((wm + _ma*16 + a_row)*SSTRIDE + (kb) + a_koff)*2u; \
        ldsm_x4(AH[_ma], _adr);                                                   \
        ldsm_x4(AL[_ma], _adr + (unsigned)TILE_B);                                \
    }                                                                             \
    _Pragma("unroll")                                                             \
    for (int _g = 0; _g < 2; _g++) {                                              \
        unsigned _bdr = stA + (unsigned)(2*TILE_B)                                \
                     + (unsigned)((wn + _g*16 + b_row)*SSTRIDE + (kb) + b_koff)*2u; \
        ldsm_x4(BH[_g], _bdr);                                                    \
        ldsm_x4(BL[_g], _bdr + (unsigned)TILE_B);                                 \
    }                                                                             \
} while(0)

#define MMA_PASS(AF, BF) do {                                                     \
    _Pragma("unroll")                                                             \
    for (int _ma = 0; _ma < 2; _ma++)                                             \
        _Pragma("unroll")                                                         \
        for (int _nb = 0; _nb < 4; _nb++)                                         \
            mma16816(acc[_ma][_nb], AF[_ma], &BF[_nb>>1][(_nb&1)*2]);             \
} while(0)

__global__ __launch_bounds__(512, 1)
void gemm_hmma_kernel(const float* __restrict__ w2) {
    extern __shared__ __half sh[];
    const unsigned shs = smem_u32(sh);
    const int tid  = threadIdx.x;
    const int warp = tid >> 5, lane = tid & 31;
    const int gid  = lane >> 2, t4 = lane & 3;
    const int bn = blockIdx.x * 128, bm = blockIdx.y * 128;
    const int wm = (warp >> 2) * 32, wn = (warp & 3) * 32;

    const int ar  = tid >> 2;
    const int akk = (tid & 3) * 8;
    const __half* srcAh = g_Ah + (size_t)(bm + ar) * DIM + akk;
    const __half* srcAl = g_Al + (size_t)(bm + ar) * DIM + akk;
    const __half* srcBh = g_Wh + (size_t)(bn + ar) * DIM + akk;
    const __half* srcBl = g_Wl + (size_t)(bn + ar) * DIM + akk;
    const unsigned dstOff = (unsigned)(ar * SSTRIDE + akk) * 2u;

    const int a_row = lane & 15;
    const int a_koff = (lane >> 4) * 8;
    const int b_row = (lane & 7) + ((lane >> 4) << 3);
    const int b_koff = ((lane >> 3) & 1) * 8;

    float acc[2][4][4];
    #pragma unroll
    for (int i = 0; i < 2; i++)
        #pragma unroll
        for (int j = 0; j < 4; j++)
            #pragma unroll
            for (int e = 0; e < 4; e++) acc[i][j][e] = 0.f;

    #pragma unroll
    for (int cc = 0; cc < NSTAGE-1; cc++) {
        unsigned sb = shs + (unsigned)(cc * STAGE_B) + dstOff;
        cp16(sb,            srcAh + cc*KC);
        cp16(sb + TILE_B,   srcAl + cc*KC);
        cp16(sb + 2*TILE_B, srcBh + cc*KC);
        cp16(sb + 3*TILE_B, srcBl + cc*KC);
        CP_COMMIT();
    }

    for (int c = 0; c < NKCHUNK; c++) {
        int rem = NKCHUNK - 1 - c;
        if (rem >= NSTAGE-2) CP_WAIT(NSTAGE-2);
        else if (rem == 1)   CP_WAIT(1);
        else                 CP_WAIT(0);
        __syncthreads();

        {
            const unsigned stA = shs + (unsigned)((c & (NSTAGE-1)) * STAGE_B);
            unsigned ah0[2][4], al0[2][4], bh0[2][4], bl0[2][4];
            unsigned ah1[2][4], al1[2][4], bh1[2][4], bl1[2][4];
            LDFRAG(ah0, al0, bh0, bl0, 0);
            MMA_PASS(ah0, bh0);                      // hh ks0
            LDFRAG(ah1, al1, bh1, bl1, 16);          // overlaps hh ks0 MMAs
            MMA_PASS(ah0, bl0);                      // hl ks0
            MMA_PASS(al0, bh0);                      // lh ks0
            MMA_PASS(ah1, bh1);                      // hh ks1
            MMA_PASS(ah1, bl1);                      // hl ks1
            MMA_PASS(al1, bh1);                      // lh ks1
        }
        int cc = c + NSTAGE - 1;
        if (cc < NKCHUNK) {
            unsigned sb = shs + (unsigned)((cc & (NSTAGE-1)) * STAGE_B) + dstOff;
            cp16(sb,            srcAh + cc*KC);
            cp16(sb + TILE_B,   srcAl + cc*KC);
            cp16(sb + 2*TILE_B, srcBh + cc*KC);
            cp16(sb + 3*TILE_B, srcBl + cc*KC);
            CP_COMMIT();
        }
    }
    __syncthreads();

    // ---- fused epilogue (single accumulator; no recombine) ----
    if (blockIdx.x == 0) {
        float* ftile = (float*)sh;                    // [128][FSTRIDE]
        float* sred  = ftile + 128*FSTRIDE;           // [128][4]
        #pragma unroll
        for (int ma = 0; ma < 2; ma++) {
            int r0 = wm + ma*16 + gid;
            #pragma unroll
            for (int nb = 0; nb < 4; nb++) {
                int c0 = wn + nb*8 + 2*t4;
                float cv0 = g_cvec[c0], cv1 = g_cvec[c0+1];
                ftile[r0*FSTRIDE + c0]       = acc[ma][nb][0] + cv0;
                ftile[r0*FSTRIDE + c0 + 1]   = acc[ma][nb][1] + cv1;
                ftile[(r0+8)*FSTRIDE + c0]   = acc[ma][nb][2] + cv0;
                ftile[(r0+8)*FSTRIDE + c0+1] = acc[ma][nb][3] + cv1;
            }
        }
        __syncthreads();
        int row = tid >> 2, seg = tid & 3;
        const float* fr = ftile + row*FSTRIDE + seg*32;
        float ss = 0.f;
        #pragma unroll
        for (int j = 0; j < 32; j++) { float v = fr[j]; ss += v*v; }
        sred[row*4 + seg] = ss;
        __syncthreads();
        float nrm = sqrtf(sred[row*4+0] + sred[row*4+1] + sred[row*4+2] + sred[row*4+3]);
        float* dst = g_mnorm + (size_t)(bm + row)*MDIM + seg*32;
        #pragma unroll
        for (int j = 0; j < 32; j++) dst[j] = fr[j] / nrm;
    } else {
        float sp[4] = {0.f, 0.f, 0.f, 0.f};
        #pragma unroll
        for (int ma = 0; ma < 2; ma++) {
            #pragma unroll
            for (int nb = 0; nb < 4; nb++) {
                int c0 = wn + nb*8 + 2*t4;
                float cv0 = g_cvec[bn + c0], cv1 = g_cvec[bn + c0 + 1];
                float w20 = w2[bn - MDIM + c0], w21 = w2[bn - MDIM + c0 + 1];
                float v00 = acc[ma][nb][0] + cv0;
                float v01 = acc[ma][nb][1] + cv1;
                float v10 = acc[ma][nb][2] + cv0;
                float v11 = acc[ma][nb][3] + cv1;
                sp[2*ma]   += fmaxf(v00, 0.f)*w20 + fmaxf(v01, 0.f)*w21;
                sp[2*ma+1] += fmaxf(v10, 0.f)*w20 + fmaxf(v11, 0.f)*w21;
            }
        }
        #pragma unroll
        for (int s = 0; s < 4; s++) {
            sp[s] += __shfl_xor_sync(0xffffffffu, sp[s], 1);
            sp[s] += __shfl_xor_sync(0xffffffffu, sp[s], 2);
        }
        float* red = (float*)sh;                      // [4 wn][128 rows]
        __syncthreads();
        if (t4 == 0) {
            int wncol = warp & 3;
            red[wncol*128 + wm + gid]          = sp[0];
            red[wncol*128 + wm + gid + 8]      = sp[1];
            red[wncol*128 + wm + 16 + gid]     = sp[2];
            red[wncol*128 + wm + 16 + gid + 8] = sp[3];
        }
        __syncthreads();
        if (tid < 128) {
            float p = red[tid] + red[128 + tid] + red[256 + tid] + red[384 + tid];
            g_impPart[(size_t)(blockIdx.x - 1)*NTOK + bm + tid] = p;
        }
    }
}

// ---------------- K3: per-window sim + greedy matching (sigmoid fused) ------
__global__ void match_kernel(const float* __restrict__ b2) {
    __shared__ float sm[4][WIN*MDIM];
    int warp = blockIdx.x * 4 + (threadIdx.x >> 5);
    int lane = threadIdx.x & 31;
    int b = warp / NW, w = warp % NW;
    int base_t = b * TSEQ + w * WIN;
    float* mwin = sm[threadIdx.x >> 5];
    float b2v = b2[0];

    const float4* src = (const float4*)(g_mnorm + (size_t)base_t * MDIM);
    for (int i = lane; i < WIN*MDIM/4; i += 32) ((float4*)mwin)[i] = src[i];
    __syncwarp();

    float sv[2];
    #pragma unroll
    for (int q = 0; q < 2; q++) {
        int f = lane + q*32;
        int a = f >> 3, c = f & 7;
        const float* va = mwin + (2*a) * MDIM;
        const float* vb = mwin + (2*c + 1) * MDIM;
        float acc = 0.f;
        #pragma unroll 8
        for (int d = 0; d < MDIM; d++) acc += va[d] * vb[d];
        sv[q] = (acc < -10.0f) ? -INFINITY : acc;
    }

    unsigned rowAvail = 0xFF, colAvail = 0xFF;
    int myA = 0, myC = 0; float myV = 0.f;
    #pragma unroll
    for (int r = 0; r < MAXP; r++) {
        float bestv = -INFINITY; int besti = 9999;
        #pragma unroll
        for (int q = 0; q < 2; q++) {
            int f = lane + q*32;
            int a = f >> 3, c = f & 7;
            bool av = ((rowAvail >> a) & 1) && ((colAvail >> c) & 1);
            float v = av ? sv[q] : -INFINITY;
            int   idx = av ? f : 9999;
            if (v > bestv || (v == bestv && idx < besti)) { bestv = v; besti = idx; }
        }
        #pragma unroll
        for (int o = 16; o; o >>= 1) {
            float ov = __shfl_xor_sync(0xffffffffu, bestv, o);
            int   oi = __shfl_xor_sync(0xffffffffu, besti, o);
            if (ov > bestv || (ov == bestv && oi < besti)) { bestv = ov; besti = oi; }
        }
        int a = besti >> 3, c = besti & 7;
        rowAvail &= ~(1u << a);
        colAvail &= ~(1u << c);
        if (lane == r) { myA = a; myC = c; myV = bestv; }
    }

    if (lane < MAXP) {
        int i_loc = w*WIN + 2*myA;
        int j_loc = w*WIN + 2*myC + 1;
        int ti = b*TSEQ + i_loc, tj = b*TSEQ + j_loc;
        float si = b2v + g_impPart[ti] + g_impPart[NTOK + ti] + g_impPart[2*NTOK + ti] + g_impPart[3*NTOK + ti];
        float sj = b2v + g_impPart[tj] + g_impPart[NTOK + tj] + g_impPart[2*NTOK + tj] + g_impPart[3*NTOK + tj];
        float ii = 1.f / (1.f + expf(-si));
        float ij = 1.f / (1.f + expf(-sj));
        int p = b*PPAIR + w*MAXP + lane;
        g_pi[p] = i_loc;
        g_pj[p] = j_loc;
        g_ps[p] = myV - 0.25f * (ii + ij);
        g_pal[p] = 1.f / (1.f + expf(-5.f * (ii - ij)));
    }
}

// ---------------- K4: per-batch top-K, scatter, prefix-scan, inverse map ----
__global__ void select_pack_kernel() {
    int b = blockIdx.x;
    int tid = threadIdx.x;
    __shared__ float svv[1024];
    __shared__ int   sii[1024];
    __shared__ int   sdrop[TSEQ];
    __shared__ int   sc[1024];

    svv[tid] = (tid < PPAIR) ? g_ps[b*PPAIR + tid] : -INFINITY;
    sii[tid] = tid;
    __syncthreads();

    for (int ksz = 2; ksz <= 1024; ksz <<= 1) {
        for (int jsz = ksz >> 1; jsz > 0; jsz >>= 1) {
            int ixj = tid ^ jsz;
            if (ixj > tid) {
                float v1 = svv[tid], v2 = svv[ixj];
                int   i1 = sii[tid], i2 = sii[ixj];
                bool tid_before = (v1 > v2) || (v1 == v2 && i1 < i2);
                bool doswap = ((tid & ksz) == 0) ? !tid_before : tid_before;
                if (doswap) { svv[tid]=v2; svv[ixj]=v1; sii[tid]=i2; sii[ixj]=i1; }
            }
            __syncthreads();
        }
    }

    for (int t = tid; t < TSEQ; t += 1024) { sdrop[t] = 0; g_partner[b*TSEQ + t] = -1; }
    __syncthreads();

    if (tid < KSEL) {
        int p = sii[tid];
        int i = g_pi[b*PPAIR + p];
        int j = g_pj[b*PPAIR + p];
        sdrop[j] = 1;
        g_partner[b*TSEQ + i] = j;
        g_atok[b*TSEQ + i] = g_pal[b*PPAIR + p];
    }
    __syncthreads();

    int k0 = 1 - sdrop[2*tid];
    int k1 = 1 - sdrop[2*tid + 1];
    int mysum = k0 + k1;
    sc[tid] = mysum;
    __syncthreads();
    for (int off = 1; off < 1024; off <<= 1) {
        int add = (tid >= off) ? sc[tid - off] : 0;
        __syncthreads();
        sc[tid] += add;
        __syncthreads();
    }
    int excl = sc[tid] - mysum;
    if (k0) g_inv[b*TKEEP + excl]      = 2*tid;
    if (k1) g_inv[b*TKEEP + excl + k0] = 2*tid + 1;
}

// ---------------- K5: merge + compact output (output-row indexed) -----------
__global__ void pack_out_kernel(const float* __restrict__ x, float* __restrict__ out) {
    int r = blockIdx.x, b = blockIdx.y;
    int t = g_inv[b*TKEEP + r];
    int bt = b*TSEQ + t;
    const float4* xi = (const float4*)(x + (size_t)bt * DIM);
    float4* o = (float4*)(out + ((size_t)b*TKEEP + r) * DIM);
    int pj = g_partner[bt];
    if (pj < 0) {
        for (int i = threadIdx.x; i < DIM/4; i += blockDim.x) o[i] = xi[i];
    } else {
        float a  = g_atok[bt];
        float ai = a, aj = 1.f - a;
        const float4* xj = (const float4*)(x + ((size_t)b*TSEQ + pj) * DIM);
        for (int i = threadIdx.x; i < DIM/4; i += blockDim.x) {
            float4 u = xi[i], v = xj[i], m, w;
            m.x = ai*u.x + aj*v.x;  m.y = ai*u.y + aj*v.y;
            m.z = ai*u.z + aj*v.z;  m.w = ai*u.w + aj*v.w;
            w.x = u.x + (m.x - u.x); w.y = u.y + (m.y - u.y);
            w.z = u.z + (m.z - u.z); w.w = u.w + (m.w - u.w);
            o[i] = w;
        }
    }
}

// ---------------- launch ----------------------------------------------------
extern "C" void kernel_launch(void* const* d_in, const int* in_sizes, int n_in,
                              void* d_out, int out_size) {
    const float* x    = (const float*)d_in[0];
    const float* gm   = (const float*)d_in[1];
    const float* bm   = (const float*)d_in[2];
    const float* wm   = (const float*)d_in[3];
    const float* gi   = (const float*)d_in[4];
    const float* bi   = (const float*)d_in[5];
    const float* w1   = (const float*)d_in[6];
    const float* b1   = (const float*)d_in[7];
    const float* w2   = (const float*)d_in[8];
    const float* b2   = (const float*)d_in[9];
    float* out = (float*)d_out;

    cudaFuncSetAttribute(gemm_hmma_kernel, cudaFuncAttributeMaxDynamicSharedMemorySize, GEMM_SMEM);

    ln_split_kernel<<<NTOK/8, 256>>>(x);
    foldW_kernel<<<dim3(DIM/32, NCOL/32), dim3(32, 8)>>>(wm, w1, gm, gi);
    foldC_kernel<<<NCOL, 256>>>(wm, w1, bm, bi, b1);
    gemm_hmma_kernel<<<dim3(NCOL/128, NTOK/128), 512, GEMM_SMEM>>>(w2);
    match_kernel<<<(BSZ*NW)/4, 128>>>(b2);
    select_pack_kernel<<<BSZ, 1024>>>();
    pack_out_kernel<<<dim3(TKEEP, BSZ), 128>>>(x, out);
}

// round 15
// speedup vs baseline: 1.4938x; 1.4938x over previous
#include <cuda_runtime.h>
#include <cuda_fp16.h>
#include <cstdint>
#include <cstring>
#include <math.h>

#define BSZ   16
#define TSEQ  2048
#define DIM   1024
#define MDIM  128
#define HID   512
#define WIN   16
#define HALF  8
#define MAXP  6
#define NW    128
#define PPAIR 768
#define KSEL  614
#define TKEEP 1434
#define NTOK  (BSZ*TSEQ)
#define NCOL  640
#define LN_EPS 1e-5f

#define KC          32               // K chunk
#define NKCHUNK     (DIM/KC)         // 32
#define NSTAGE      4
#define SSTRIDE     40               // padded half stride per row (32 used)
#define TILE_H      (128*SSTRIDE)    // halves per plane (5120)
#define TILE_B      (TILE_H*2)       // 10240 bytes
#define STAGE_B     (4*TILE_B)       // Ah, Al, Bh, Bl = 40960 bytes
#define GEMM_SMEM   (NSTAGE*STAGE_B) // 163840 bytes
#define FSTRIDE     132              // fp32 epilogue tile stride

// ---------------- scratch ---------------------------------------------------
__device__ __half g_Ah[(size_t)NTOK*DIM];
__device__ __half g_Al[(size_t)NTOK*DIM];     // lo residual * 2048
__device__ __half g_Wh[NCOL*DIM];             // folded weights hi, [n][k]
__device__ __half g_Wl[NCOL*DIM];             // folded weights lo*2048, [n][k]
__device__ float g_cvec[NCOL];
__device__ float g_mnorm[(size_t)NTOK*MDIM];
__device__ float g_impPart[4*NTOK];
__device__ int   g_pi[BSZ*PPAIR];
__device__ int   g_pj[BSZ*PPAIR];
__device__ float g_ps[BSZ*PPAIR];
__device__ float g_pal[BSZ*PPAIR];
__device__ int   g_inv[BSZ*TKEEP];
__device__ int   g_partner[BSZ*TSEQ];
__device__ float g_atok[BSZ*TSEQ];

// ---------------- helpers ---------------------------------------------------
__device__ __forceinline__ float block_reduce_sum(float v, float* sbuf) {
    int lane = threadIdx.x & 31, wid = threadIdx.x >> 5;
    #pragma unroll
    for (int o = 16; o; o >>= 1) v += __shfl_xor_sync(0xffffffffu, v, o);
    if (lane == 0) sbuf[wid] = v;
    __syncthreads();
    int nw = blockDim.x >> 5;
    float r = (threadIdx.x < nw) ? sbuf[threadIdx.x] : 0.f;
    if (wid == 0) {
        #pragma unroll
        for (int o = 16; o; o >>= 1) r += __shfl_xor_sync(0xffffffffu, r, o);
        if (lane == 0) sbuf[0] = r;
    }
    __syncthreads();
    r = sbuf[0];
    __syncthreads();
    return r;
}

__device__ __forceinline__ float warp_sum(float v) {
    #pragma unroll
    for (int o = 16; o; o >>= 1) v += __shfl_xor_sync(0xffffffffu, v, o);
    return v;
}

__device__ __forceinline__ void mma16816(float c[4], const unsigned a[4], const unsigned b[2]) {
    asm volatile("mma.sync.aligned.m16n8k16.row.col.f32.f16.f16.f32 "
        "{%0,%1,%2,%3}, {%4,%5,%6,%7}, {%8,%9}, {%0,%1,%2,%3};"
        : "+f"(c[0]), "+f"(c[1]), "+f"(c[2]), "+f"(c[3])
        : "r"(a[0]), "r"(a[1]), "r"(a[2]), "r"(a[3]), "r"(b[0]), "r"(b[1]));
}

__device__ __forceinline__ void ldsm_x4(unsigned r[4], unsigned addr) {
    asm volatile("ldmatrix.sync.aligned.m8n8.x4.shared.b16 {%0,%1,%2,%3}, [%4];"
        : "=r"(r[0]), "=r"(r[1]), "=r"(r[2]), "=r"(r[3]) : "r"(addr));
}

__device__ __forceinline__ unsigned smem_u32(const void* p) {
    unsigned a;
    asm("{ .reg .u64 t; cvta.to.shared.u64 t, %1; cvt.u32.u64 %0, t; }" : "=r"(a) : "l"(p));
    return a;
}

__device__ __forceinline__ void cp16(unsigned dst, const void* src) {
    asm volatile("cp.async.cg.shared.global [%0], [%1], 16;" :: "r"(dst), "l"(src));
}
#define CP_COMMIT() asm volatile("cp.async.commit_group;" ::: "memory")
#define CP_WAIT(N)  asm volatile("cp.async.wait_group %0;" :: "n"(N) : "memory")

__device__ __forceinline__ unsigned pack_h2(__half a, __half b) {
    __half2 h = __halves2half2(a, b);
    unsigned u; memcpy(&u, &h, 4); return u;
}

// ---------------- K0: LN + split, warp-per-token ----------------------------
__global__ void ln_split_kernel(const float* __restrict__ x) {
    int t = blockIdx.x * 8 + (threadIdx.x >> 5);
    int lane = threadIdx.x & 31;
    const float4* row = (const float4*)(x + (size_t)t * DIM);
    float4 v[8];
    float s = 0.f;
    #pragma unroll
    for (int j = 0; j < 8; j++) {
        v[j] = row[lane + 32*j];
        s += v[j].x + v[j].y + v[j].z + v[j].w;
    }
    float mean = warp_sum(s) * (1.0f / DIM);
    float ss = 0.f;
    #pragma unroll
    for (int j = 0; j < 8; j++) {
        float d0 = v[j].x-mean, d1 = v[j].y-mean, d2 = v[j].z-mean, d3 = v[j].w-mean;
        ss += d0*d0 + d1*d1 + d2*d2 + d3*d3;
    }
    float rs = rsqrtf(warp_sum(ss) * (1.0f / DIM) + LN_EPS);
    #pragma unroll
    for (int j = 0; j < 8; j++) {
        float f[4] = {(v[j].x-mean)*rs, (v[j].y-mean)*rs, (v[j].z-mean)*rs, (v[j].w-mean)*rs};
        unsigned hp[2], lp[2];
        #pragma unroll
        for (int e = 0; e < 2; e++) {
            __half h0 = __float2half_rn(f[2*e]),   h1 = __float2half_rn(f[2*e+1]);
            __half l0 = __float2half_rn((f[2*e]   - __half2float(h0)) * 2048.f);
            __half l1 = __float2half_rn((f[2*e+1] - __half2float(h1)) * 2048.f);
            hp[e] = pack_h2(h0, h1);  lp[e] = pack_h2(l0, l1);
        }
        size_t off = (size_t)t * DIM + (lane + 32*j) * 4;
        *(uint2*)(g_Ah + off) = make_uint2(hp[0], hp[1]);
        *(uint2*)(g_Al + off) = make_uint2(lp[0], lp[1]);
    }
}

// ---------------- fold weights into split fp16 [n][k] -----------------------
__global__ void foldW_kernel(const float* __restrict__ wm, const float* __restrict__ w1,
                             const float* __restrict__ gm, const float* __restrict__ gi) {
    __shared__ float tile[32][33];
    int k0 = blockIdx.x * 32, n0 = blockIdx.y * 32;
    int tx = threadIdx.x, ty = threadIdx.y;
    #pragma unroll
    for (int j = 0; j < 4; j++) {
        int k = k0 + ty + j*8, n = n0 + tx;
        float w = (n < MDIM) ? gm[k] * wm[k*MDIM + n]
                             : gi[k] * w1[k*HID + (n - MDIM)];
        tile[ty + j*8][tx] = w;
    }
    __syncthreads();
    #pragma unroll
    for (int j = 0; j < 4; j++) {
        int n = n0 + ty + j*8, k = k0 + tx;
        float w = tile[tx][ty + j*8];
        __half h = __float2half_rn(w);
        g_Wh[(size_t)n*DIM + k] = h;
        g_Wl[(size_t)n*DIM + k] = __float2half_rn((w - __half2float(h)) * 2048.f);
    }
}

__global__ void foldC_kernel(const float* __restrict__ wm, const float* __restrict__ w1,
                             const float* __restrict__ bm, const float* __restrict__ bi,
                             const float* __restrict__ b1) {
    int n = blockIdx.x;
    __shared__ float sbuf[32];
    float s = 0.f;
    if (n < MDIM) {
        for (int d = threadIdx.x; d < DIM; d += blockDim.x) s += bm[d] * wm[d*MDIM + n];
    } else {
        for (int d = threadIdx.x; d < DIM; d += blockDim.x) s += bi[d] * w1[d*HID + (n - MDIM)];
    }
    float tot = block_reduce_sum(s, sbuf);
    if (threadIdx.x == 0) g_cvec[n] = tot + ((n >= MDIM) ? b1[n - MDIM] : 0.f);
}

// ---------------- K1: split-fp16 HMMA GEMM (R12 best config) ----------------
// grid (5, 256): bn = 128*bx, bm = 128*by.  512 threads = 4x4 warps, 32x32/warp.
__global__ __launch_bounds__(512, 1)
void gemm_hmma_kernel(const float* __restrict__ w2) {
    extern __shared__ __half sh[];
    const unsigned shs = smem_u32(sh);
    const int tid  = threadIdx.x;
    const int warp = tid >> 5, lane = tid & 31;
    const int gid  = lane >> 2, t4 = lane & 3;
    const int bn = blockIdx.x * 128, bm = blockIdx.y * 128;
    const int wm = (warp >> 2) * 32, wn = (warp & 3) * 32;

    const int ar  = tid >> 2;
    const int akk = (tid & 3) * 8;
    const __half* srcAh = g_Ah + (size_t)(bm + ar) * DIM + akk;
    const __half* srcAl = g_Al + (size_t)(bm + ar) * DIM + akk;
    const __half* srcBh = g_Wh + (size_t)(bn + ar) * DIM + akk;
    const __half* srcBl = g_Wl + (size_t)(bn + ar) * DIM + akk;
    const unsigned dstOff = (unsigned)(ar * SSTRIDE + akk) * 2u;

    const int a_row = lane & 15;
    const int a_koff = (lane >> 4) * 8;
    const int b_row = (lane & 7) + ((lane >> 4) << 3);
    const int b_koff = ((lane >> 3) & 1) * 8;

    float acc0[2][4][4], acc1[2][4][4];
    #pragma unroll
    for (int i = 0; i < 2; i++)
        #pragma unroll
        for (int j = 0; j < 4; j++)
            #pragma unroll
            for (int e = 0; e < 4; e++) { acc0[i][j][e] = 0.f; acc1[i][j][e] = 0.f; }

    #pragma unroll
    for (int cc = 0; cc < NSTAGE-1; cc++) {
        unsigned sb = shs + (unsigned)(cc * STAGE_B) + dstOff;
        cp16(sb,            srcAh + cc*KC);
        cp16(sb + TILE_B,   srcAl + cc*KC);
        cp16(sb + 2*TILE_B, srcBh + cc*KC);
        cp16(sb + 3*TILE_B, srcBl + cc*KC);
        CP_COMMIT();
    }

    for (int c = 0; c < NKCHUNK; c++) {
        int rem = NKCHUNK - 1 - c;
        if (rem >= NSTAGE-2) CP_WAIT(NSTAGE-2);
        else if (rem == 1)   CP_WAIT(1);
        else                 CP_WAIT(0);
        __syncthreads();

        {
            const unsigned stA = shs + (unsigned)((c & (NSTAGE-1)) * STAGE_B);
            #pragma unroll
            for (int ks = 0; ks < 2; ks++) {
                const int kb = ks*16;
                unsigned ah[2][4], al[2][4], bh[2][4], bl[2][4];
                #pragma unroll
                for (int ma = 0; ma < 2; ma++) {
                    unsigned adr = stA + (unsigned)((wm + ma*16 + a_row)*SSTRIDE + kb + a_koff)*2u;
                    ldsm_x4(ah[ma], adr);
                    ldsm_x4(al[ma], adr + (unsigned)TILE_B);
                }
                #pragma unroll
                for (int g = 0; g < 2; g++) {
                    unsigned bdr = stA + (unsigned)(2*TILE_B)
                                 + (unsigned)((wn + g*16 + b_row)*SSTRIDE + kb + b_koff)*2u;
                    ldsm_x4(bh[g], bdr);
                    ldsm_x4(bl[g], bdr + (unsigned)TILE_B);
                }
                #pragma unroll
                for (int ma = 0; ma < 2; ma++)
                    #pragma unroll
                    for (int nb = 0; nb < 4; nb++)
                        mma16816(acc0[ma][nb], ah[ma], &bh[nb>>1][(nb&1)*2]);
                #pragma unroll
                for (int ma = 0; ma < 2; ma++)
                    #pragma unroll
                    for (int nb = 0; nb < 4; nb++)
                        mma16816(acc1[ma][nb], ah[ma], &bl[nb>>1][(nb&1)*2]);
                #pragma unroll
                for (int ma = 0; ma < 2; ma++)
                    #pragma unroll
                    for (int nb = 0; nb < 4; nb++)
                        mma16816(acc1[ma][nb], al[ma], &bh[nb>>1][(nb&1)*2]);
            }
        }
        int cc = c + NSTAGE - 1;
        if (cc < NKCHUNK) {
            unsigned sb = shs + (unsigned)((cc & (NSTAGE-1)) * STAGE_B) + dstOff;
            cp16(sb,            srcAh + cc*KC);
            cp16(sb + TILE_B,   srcAl + cc*KC);
            cp16(sb + 2*TILE_B, srcBh + cc*KC);
            cp16(sb + 3*TILE_B, srcBl + cc*KC);
            CP_COMMIT();
        }
    }
    __syncthreads();

    // ---- fused epilogue ----
    const float inv = 1.f / 2048.f;
    if (blockIdx.x == 0) {
        float* ftile = (float*)sh;                    // [128][FSTRIDE]
        float* sred  = ftile + 128*FSTRIDE;           // [128][4]
        #pragma unroll
        for (int ma = 0; ma < 2; ma++) {
            int r0 = wm + ma*16 + gid;
            #pragma unroll
            for (int nb = 0; nb < 4; nb++) {
                int c0 = wn + nb*8 + 2*t4;
                float cv0 = g_cvec[c0], cv1 = g_cvec[c0+1];
                ftile[r0*FSTRIDE + c0]       = acc0[ma][nb][0] + acc1[ma][nb][0]*inv + cv0;
                ftile[r0*FSTRIDE + c0 + 1]   = acc0[ma][nb][1] + acc1[ma][nb][1]*inv + cv1;
                ftile[(r0+8)*FSTRIDE + c0]   = acc0[ma][nb][2] + acc1[ma][nb][2]*inv + cv0;
                ftile[(r0+8)*FSTRIDE + c0+1] = acc0[ma][nb][3] + acc1[ma][nb][3]*inv + cv1;
            }
        }
        __syncthreads();
        int row = tid >> 2, seg = tid & 3;
        const float* fr = ftile + row*FSTRIDE + seg*32;
        float ss = 0.f;
        #pragma unroll
        for (int j = 0; j < 32; j++) { float v = fr[j]; ss += v*v; }
        sred[row*4 + seg] = ss;
        __syncthreads();
        float nrm = sqrtf(sred[row*4+0] + sred[row*4+1] + sred[row*4+2] + sred[row*4+3]);
        float* dst = g_mnorm + (size_t)(bm + row)*MDIM + seg*32;
        #pragma unroll
        for (int j = 0; j < 32; j++) dst[j] = fr[j] / nrm;
    } else {
        float sp[4] = {0.f, 0.f, 0.f, 0.f};
        #pragma unroll
        for (int ma = 0; ma < 2; ma++) {
            #pragma unroll
            for (int nb = 0; nb < 4; nb++) {
                int c0 = wn + nb*8 + 2*t4;
                float cv0 = g_cvec[bn + c0], cv1 = g_cvec[bn + c0 + 1];
                float w20 = w2[bn - MDIM + c0], w21 = w2[bn - MDIM + c0 + 1];
                float v00 = acc0[ma][nb][0] + acc1[ma][nb][0]*inv + cv0;
                float v01 = acc0[ma][nb][1] + acc1[ma][nb][1]*inv + cv1;
                float v10 = acc0[ma][nb][2] + acc1[ma][nb][2]*inv + cv0;
                float v11 = acc0[ma][nb][3] + acc1[ma][nb][3]*inv + cv1;
                sp[2*ma]   += fmaxf(v00, 0.f)*w20 + fmaxf(v01, 0.f)*w21;
                sp[2*ma+1] += fmaxf(v10, 0.f)*w20 + fmaxf(v11, 0.f)*w21;
            }
        }
        #pragma unroll
        for (int s = 0; s < 4; s++) {
            sp[s] += __shfl_xor_sync(0xffffffffu, sp[s], 1);
            sp[s] += __shfl_xor_sync(0xffffffffu, sp[s], 2);
        }
        float* red = (float*)sh;                      // [4 wn][128 rows]
        __syncthreads();
        if (t4 == 0) {
            int wncol = warp & 3;
            red[wncol*128 + wm + gid]          = sp[0];
            red[wncol*128 + wm + gid + 8]      = sp[1];
            red[wncol*128 + wm + 16 + gid]     = sp[2];
            red[wncol*128 + wm + 16 + gid + 8] = sp[3];
        }
        __syncthreads();
        if (tid < 128) {
            float p = red[tid] + red[128 + tid] + red[256 + tid] + red[384 + tid];
            g_impPart[(size_t)(blockIdx.x - 1)*NTOK + bm + tid] = p;
        }
    }
}

// ---------------- K3: per-window sim + greedy matching (sigmoid fused) ------
__global__ void match_kernel(const float* __restrict__ b2) {
    __shared__ float sm[4][WIN*MDIM];
    int warp = blockIdx.x * 4 + (threadIdx.x >> 5);
    int lane = threadIdx.x & 31;
    int b = warp / NW, w = warp % NW;
    int base_t = b * TSEQ + w * WIN;
    float* mwin = sm[threadIdx.x >> 5];
    float b2v = b2[0];

    const float4* src = (const float4*)(g_mnorm + (size_t)base_t * MDIM);
    for (int i = lane; i < WIN*MDIM/4; i += 32) ((float4*)mwin)[i] = src[i];
    __syncwarp();

    float sv[2];
    #pragma unroll
    for (int q = 0; q < 2; q++) {
        int f = lane + q*32;
        int a = f >> 3, c = f & 7;
        const float* va = mwin + (2*a) * MDIM;
        const float* vb = mwin + (2*c + 1) * MDIM;
        float acc = 0.f;
        #pragma unroll 8
        for (int d = 0; d < MDIM; d++) acc += va[d] * vb[d];
        sv[q] = (acc < -10.0f) ? -INFINITY : acc;
    }

    unsigned rowAvail = 0xFF, colAvail = 0xFF;
    int myA = 0, myC = 0; float myV = 0.f;
    #pragma unroll
    for (int r = 0; r < MAXP; r++) {
        float bestv = -INFINITY; int besti = 9999;
        #pragma unroll
        for (int q = 0; q < 2; q++) {
            int f = lane + q*32;
            int a = f >> 3, c = f & 7;
            bool av = ((rowAvail >> a) & 1) && ((colAvail >> c) & 1);
            float v = av ? sv[q] : -INFINITY;
            int   idx = av ? f : 9999;
            if (v > bestv || (v == bestv && idx < besti)) { bestv = v; besti = idx; }
        }
        #pragma unroll
        for (int o = 16; o; o >>= 1) {
            float ov = __shfl_xor_sync(0xffffffffu, bestv, o);
            int   oi = __shfl_xor_sync(0xffffffffu, besti, o);
            if (ov > bestv || (ov == bestv && oi < besti)) { bestv = ov; besti = oi; }
        }
        int a = besti >> 3, c = besti & 7;
        rowAvail &= ~(1u << a);
        colAvail &= ~(1u << c);
        if (lane == r) { myA = a; myC = c; myV = bestv; }
    }

    if (lane < MAXP) {
        int i_loc = w*WIN + 2*myA;
        int j_loc = w*WIN + 2*myC + 1;
        int ti = b*TSEQ + i_loc, tj = b*TSEQ + j_loc;
        float si = b2v + g_impPart[ti] + g_impPart[NTOK + ti] + g_impPart[2*NTOK + ti] + g_impPart[3*NTOK + ti];
        float sj = b2v + g_impPart[tj] + g_impPart[NTOK + tj] + g_impPart[2*NTOK + tj] + g_impPart[3*NTOK + tj];
        float ii = 1.f / (1.f + expf(-si));
        float ij = 1.f / (1.f + expf(-sj));
        int p = b*PPAIR + w*MAXP + lane;
        g_pi[p] = i_loc;
        g_pj[p] = j_loc;
        g_ps[p] = myV - 0.25f * (ii + ij);
        g_pal[p] = 1.f / (1.f + expf(-5.f * (ii - ij)));
    }
}

// ---------------- K4: per-batch top-K, scatter, shfl-scan, inverse map ------
__global__ void select_pack_kernel() {
    int b = blockIdx.x;
    int tid = threadIdx.x;
    int lane = tid & 31, wrp = tid >> 5;
    __shared__ float svv[1024];
    __shared__ int   sii[1024];
    __shared__ int   sdrop[TSEQ];
    __shared__ int   wsum[32];

    svv[tid] = (tid < PPAIR) ? g_ps[b*PPAIR + tid] : -INFINITY;
    sii[tid] = tid;
    __syncthreads();

    for (int ksz = 2; ksz <= 1024; ksz <<= 1) {
        for (int jsz = ksz >> 1; jsz > 0; jsz >>= 1) {
            int ixj = tid ^ jsz;
            if (ixj > tid) {
                float v1 = svv[tid], v2 = svv[ixj];
                int   i1 = sii[tid], i2 = sii[ixj];
                bool tid_before = (v1 > v2) || (v1 == v2 && i1 < i2);
                bool doswap = ((tid & ksz) == 0) ? !tid_before : tid_before;
                if (doswap) { svv[tid]=v2; svv[ixj]=v1; sii[tid]=i2; sii[ixj]=i1; }
            }
            __syncthreads();
        }
    }

    for (int t = tid; t < TSEQ; t += 1024) { sdrop[t] = 0; g_partner[b*TSEQ + t] = -1; }
    __syncthreads();

    if (tid < KSEL) {
        int p = sii[tid];
        int i = g_pi[b*PPAIR + p];
        int j = g_pj[b*PPAIR + p];
        sdrop[j] = 1;
        g_partner[b*TSEQ + i] = j;
        g_atok[b*TSEQ + i] = g_pal[b*PPAIR + p];
    }
    __syncthreads();

    int k0 = 1 - sdrop[2*tid];
    int k1 = 1 - sdrop[2*tid + 1];
    int mysum = k0 + k1;

    // warp inclusive scan
    int v = mysum;
    #pragma unroll
    for (int o = 1; o < 32; o <<= 1) {
        int n = __shfl_up_sync(0xffffffffu, v, o);
        if (lane >= o) v += n;
    }
    if (lane == 31) wsum[wrp] = v;
    __syncthreads();
    if (wrp == 0) {
        int wv = wsum[lane];
        #pragma unroll
        for (int o = 1; o < 32; o <<= 1) {
            int n = __shfl_up_sync(0xffffffffu, wv, o);
            if (lane >= o) wv += n;
        }
        wsum[lane] = wv;
    }
    __syncthreads();
    int incl = v + (wrp ? wsum[wrp - 1] : 0);
    int excl = incl - mysum;
    if (k0) g_inv[b*TKEEP + excl]      = 2*tid;
    if (k1) g_inv[b*TKEEP + excl + k0] = 2*tid + 1;
}

// ---------------- K5: merge + compact output (output-row indexed) -----------
__global__ void pack_out_kernel(const float* __restrict__ x, float* __restrict__ out) {
    int r = blockIdx.x, b = blockIdx.y;
    int t = g_inv[b*TKEEP + r];
    int bt = b*TSEQ + t;
    const float4* xi = (const float4*)(x + (size_t)bt * DIM);
    float4* o = (float4*)(out + ((size_t)b*TKEEP + r) * DIM);
    int pj = g_partner[bt];
    if (pj < 0) {
        for (int i = threadIdx.x; i < DIM/4; i += blockDim.x) o[i] = xi[i];
    } else {
        float a  = g_atok[bt];
        float ai = a, aj = 1.f - a;
        const float4* xj = (const float4*)(x + ((size_t)b*TSEQ + pj) * DIM);
        for (int i = threadIdx.x; i < DIM/4; i += blockDim.x) {
            float4 u = xi[i], v = xj[i], m, w;
            m.x = ai*u.x + aj*v.x;  m.y = ai*u.y + aj*v.y;
            m.z = ai*u.z + aj*v.z;  m.w = ai*u.w + aj*v.w;
            w.x = u.x + (m.x - u.x); w.y = u.y + (m.y - u.y);
            w.z = u.z + (m.z - u.z); w.w = u.w + (m.w - u.w);
            o[i] = w;
        }
    }
}

// ---------------- launch ----------------------------------------------------
extern "C" void kernel_launch(void* const* d_in, const int* in_sizes, int n_in,
                              void* d_out, int out_size) {
    const float* x    = (const float*)d_in[0];
    const float* gm   = (const float*)d_in[1];
    const float* bm   = (const float*)d_in[2];
    const float* wm   = (const float*)d_in[3];
    const float* gi   = (const float*)d_in[4];
    const float* bi   = (const float*)d_in[5];
    const float* w1   = (const float*)d_in[6];
    const float* b1   = (const float*)d_in[7];
    const float* w2   = (const float*)d_in[8];
    const float* b2   = (const float*)d_in[9];
    float* out = (float*)d_out;

    cudaFuncSetAttribute(gemm_hmma_kernel, cudaFuncAttributeMaxDynamicSharedMemorySize, GEMM_SMEM);

    ln_split_kernel<<<NTOK/8, 256>>>(x);
    foldW_kernel<<<dim3(DIM/32, NCOL/32), dim3(32, 8)>>>(wm, w1, gm, gi);
    foldC_kernel<<<NCOL, 256>>>(wm, w1, bm, bi, b1);
    gemm_hmma_kernel<<<dim3(NCOL/128, NTOK/128), 512, GEMM_SMEM>>>(w2);
    match_kernel<<<(BSZ*NW)/4, 128>>>(b2);
    select_pack_kernel<<<BSZ, 1024>>>();
    pack_out_kernel<<<dim3(TKEEP, BSZ), 128>>>(x, out);
}

// round 16
// speedup vs baseline: 1.6261x; 1.0886x over previous
#include <cuda_runtime.h>
#include <cuda_fp16.h>
#include <cstdint>
#include <cstring>
#include <math.h>

#define BSZ   16
#define TSEQ  2048
#define DIM   1024
#define MDIM  128
#define HID   512
#define WIN   16
#define HALF  8
#define MAXP  6
#define NW    128
#define PPAIR 768
#define KSEL  614
#define TKEEP 1434
#define NTOK  (BSZ*TSEQ)
#define NCOL  640
#define LN_EPS 1e-5f

#define KC          32               // K chunk
#define NKCHUNK     (DIM/KC)         // 32
#define NSTAGE      4
#define SSTRIDE     40               // padded half stride per row (32 used)
#define TILE_H      (128*SSTRIDE)    // halves per plane (5120)
#define TILE_B      (TILE_H*2)       // 10240 bytes
#define STAGE_B     (4*TILE_B)       // Ah, Al, Bh, Bl = 40960 bytes
#define GEMM_SMEM   (NSTAGE*STAGE_B) // 163840 bytes
#define FSTRIDE     132              // fp32 epilogue tile stride

// ---------------- scratch ---------------------------------------------------
__device__ __half g_Ah[(size_t)NTOK*DIM];
__device__ __half g_Al[(size_t)NTOK*DIM];     // lo residual * 2048
__device__ __half g_Wh[NCOL*DIM];             // folded weights hi, [n][k]
__device__ __half g_Wl[NCOL*DIM];             // folded weights lo*2048, [n][k]
__device__ float g_cvec[NCOL];
__device__ float g_impPart[4*NTOK];
__device__ int   g_pi[BSZ*PPAIR];
__device__ int   g_pj[BSZ*PPAIR];
__device__ float g_sv[BSZ*PPAIR];
__device__ float g_ps[BSZ*PPAIR];
__device__ float g_pal[BSZ*PPAIR];
__device__ int   g_inv[BSZ*TKEEP];
__device__ int   g_partner[BSZ*TSEQ];
__device__ float g_atok[BSZ*TSEQ];

// ---------------- helpers ---------------------------------------------------
__device__ __forceinline__ float block_reduce_sum(float v, float* sbuf) {
    int lane = threadIdx.x & 31, wid = threadIdx.x >> 5;
    #pragma unroll
    for (int o = 16; o; o >>= 1) v += __shfl_xor_sync(0xffffffffu, v, o);
    if (lane == 0) sbuf[wid] = v;
    __syncthreads();
    int nw = blockDim.x >> 5;
    float r = (threadIdx.x < nw) ? sbuf[threadIdx.x] : 0.f;
    if (wid == 0) {
        #pragma unroll
        for (int o = 16; o; o >>= 1) r += __shfl_xor_sync(0xffffffffu, r, o);
        if (lane == 0) sbuf[0] = r;
    }
    __syncthreads();
    r = sbuf[0];
    __syncthreads();
    return r;
}

__device__ __forceinline__ float warp_sum(float v) {
    #pragma unroll
    for (int o = 16; o; o >>= 1) v += __shfl_xor_sync(0xffffffffu, v, o);
    return v;
}

__device__ __forceinline__ void mma16816(float c[4], const unsigned a[4], const unsigned b[2]) {
    asm volatile("mma.sync.aligned.m16n8k16.row.col.f32.f16.f16.f32 "
        "{%0,%1,%2,%3}, {%4,%5,%6,%7}, {%8,%9}, {%0,%1,%2,%3};"
        : "+f"(c[0]), "+f"(c[1]), "+f"(c[2]), "+f"(c[3])
        : "r"(a[0]), "r"(a[1]), "r"(a[2]), "r"(a[3]), "r"(b[0]), "r"(b[1]));
}

__device__ __forceinline__ void ldsm_x4(unsigned r[4], unsigned addr) {
    asm volatile("ldmatrix.sync.aligned.m8n8.x4.shared.b16 {%0,%1,%2,%3}, [%4];"
        : "=r"(r[0]), "=r"(r[1]), "=r"(r[2]), "=r"(r[3]) : "r"(addr));
}

__device__ __forceinline__ unsigned smem_u32(const void* p) {
    unsigned a;
    asm("{ .reg .u64 t; cvta.to.shared.u64 t, %1; cvt.u32.u64 %0, t; }" : "=r"(a) : "l"(p));
    return a;
}

__device__ __forceinline__ void cp16(unsigned dst, const void* src) {
    asm volatile("cp.async.cg.shared.global [%0], [%1], 16;" :: "r"(dst), "l"(src));
}
#define CP_COMMIT() asm volatile("cp.async.commit_group;" ::: "memory")
#define CP_WAIT(N)  asm volatile("cp.async.wait_group %0;" :: "n"(N) : "memory")

__device__ __forceinline__ unsigned pack_h2(__half a, __half b) {
    __half2 h = __halves2half2(a, b);
    unsigned u; memcpy(&u, &h, 4); return u;
}

// ---------------- K0: LN + split, warp-per-token ----------------------------
__global__ void ln_split_kernel(const float* __restrict__ x) {
    int t = blockIdx.x * 8 + (threadIdx.x >> 5);
    int lane = threadIdx.x & 31;
    const float4* row = (const float4*)(x + (size_t)t * DIM);
    float4 v[8];
    float s = 0.f;
    #pragma unroll
    for (int j = 0; j < 8; j++) {
        v[j] = row[lane + 32*j];
        s += v[j].x + v[j].y + v[j].z + v[j].w;
    }
    float mean = warp_sum(s) * (1.0f / DIM);
    float ss = 0.f;
    #pragma unroll
    for (int j = 0; j < 8; j++) {
        float d0 = v[j].x-mean, d1 = v[j].y-mean, d2 = v[j].z-mean, d3 = v[j].w-mean;
        ss += d0*d0 + d1*d1 + d2*d2 + d3*d3;
    }
    float rs = rsqrtf(warp_sum(ss) * (1.0f / DIM) + LN_EPS);
    #pragma unroll
    for (int j = 0; j < 8; j++) {
        float f[4] = {(v[j].x-mean)*rs, (v[j].y-mean)*rs, (v[j].z-mean)*rs, (v[j].w-mean)*rs};
        unsigned hp[2], lp[2];
        #pragma unroll
        for (int e = 0; e < 2; e++) {
            __half h0 = __float2half_rn(f[2*e]),   h1 = __float2half_rn(f[2*e+1]);
            __half l0 = __float2half_rn((f[2*e]   - __half2float(h0)) * 2048.f);
            __half l1 = __float2half_rn((f[2*e+1] - __half2float(h1)) * 2048.f);
            hp[e] = pack_h2(h0, h1);  lp[e] = pack_h2(l0, l1);
        }
        size_t off = (size_t)t * DIM + (lane + 32*j) * 4;
        *(uint2*)(g_Ah + off) = make_uint2(hp[0], hp[1]);
        *(uint2*)(g_Al + off) = make_uint2(lp[0], lp[1]);
    }
}

// ---------------- fold weights into split fp16 [n][k] -----------------------
__global__ void foldW_kernel(const float* __restrict__ wm, const float* __restrict__ w1,
                             const float* __restrict__ gm, const float* __restrict__ gi) {
    __shared__ float tile[32][33];
    int k0 = blockIdx.x * 32, n0 = blockIdx.y * 32;
    int tx = threadIdx.x, ty = threadIdx.y;
    #pragma unroll
    for (int j = 0; j < 4; j++) {
        int k = k0 + ty + j*8, n = n0 + tx;
        float w = (n < MDIM) ? gm[k] * wm[k*MDIM + n]
                             : gi[k] * w1[k*HID + (n - MDIM)];
        tile[ty + j*8][tx] = w;
    }
    __syncthreads();
    #pragma unroll
    for (int j = 0; j < 4; j++) {
        int n = n0 + ty + j*8, k = k0 + tx;
        float w = tile[tx][ty + j*8];
        __half h = __float2half_rn(w);
        g_Wh[(size_t)n*DIM + k] = h;
        g_Wl[(size_t)n*DIM + k] = __float2half_rn((w - __half2float(h)) * 2048.f);
    }
}

__global__ void foldC_kernel(const float* __restrict__ wm, const float* __restrict__ w1,
                             const float* __restrict__ bm, const float* __restrict__ bi,
                             const float* __restrict__ b1) {
    int n = blockIdx.x;
    __shared__ float sbuf[32];
    float s = 0.f;
    if (n < MDIM) {
        for (int d = threadIdx.x; d < DIM; d += blockDim.x) s += bm[d] * wm[d*MDIM + n];
    } else {
        for (int d = threadIdx.x; d < DIM; d += blockDim.x) s += bi[d] * w1[d*HID + (n - MDIM)];
    }
    float tot = block_reduce_sum(s, sbuf);
    if (threadIdx.x == 0) g_cvec[n] = tot + ((n >= MDIM) ? b1[n - MDIM] : 0.f);
}

// ---------------- K1: split-fp16 HMMA GEMM + fused match (bx=0) -------------
// grid (5, 256): bn = 128*bx, bm = 128*by.  512 threads = 4x4 warps, 32x32/warp.
__global__ __launch_bounds__(512, 1)
void gemm_hmma_kernel(const float* __restrict__ w2) {
    extern __shared__ __half sh[];
    const unsigned shs = smem_u32(sh);
    const int tid  = threadIdx.x;
    const int warp = tid >> 5, lane = tid & 31;
    const int gid  = lane >> 2, t4 = lane & 3;
    const int bn = blockIdx.x * 128, bm = blockIdx.y * 128;
    const int wm = (warp >> 2) * 32, wn = (warp & 3) * 32;

    const int ar  = tid >> 2;
    const int akk = (tid & 3) * 8;
    const __half* srcAh = g_Ah + (size_t)(bm + ar) * DIM + akk;
    const __half* srcAl = g_Al + (size_t)(bm + ar) * DIM + akk;
    const __half* srcBh = g_Wh + (size_t)(bn + ar) * DIM + akk;
    const __half* srcBl = g_Wl + (size_t)(bn + ar) * DIM + akk;
    const unsigned dstOff = (unsigned)(ar * SSTRIDE + akk) * 2u;

    const int a_row = lane & 15;
    const int a_koff = (lane >> 4) * 8;
    const int b_row = (lane & 7) + ((lane >> 4) << 3);
    const int b_koff = ((lane >> 3) & 1) * 8;

    float acc0[2][4][4], acc1[2][4][4];
    #pragma unroll
    for (int i = 0; i < 2; i++)
        #pragma unroll
        for (int j = 0; j < 4; j++)
            #pragma unroll
            for (int e = 0; e < 4; e++) { acc0[i][j][e] = 0.f; acc1[i][j][e] = 0.f; }

    #pragma unroll
    for (int cc = 0; cc < NSTAGE-1; cc++) {
        unsigned sb = shs + (unsigned)(cc * STAGE_B) + dstOff;
        cp16(sb,            srcAh + cc*KC);
        cp16(sb + TILE_B,   srcAl + cc*KC);
        cp16(sb + 2*TILE_B, srcBh + cc*KC);
        cp16(sb + 3*TILE_B, srcBl + cc*KC);
        CP_COMMIT();
    }

    for (int c = 0; c < NKCHUNK; c++) {
        int rem = NKCHUNK - 1 - c;
        if (rem >= NSTAGE-2) CP_WAIT(NSTAGE-2);
        else if (rem == 1)   CP_WAIT(1);
        else                 CP_WAIT(0);
        __syncthreads();

        {
            const unsigned stA = shs + (unsigned)((c & (NSTAGE-1)) * STAGE_B);
            #pragma unroll
            for (int ks = 0; ks < 2; ks++) {
                const int kb = ks*16;
                unsigned ah[2][4], al[2][4], bh[2][4], bl[2][4];
                #pragma unroll
                for (int ma = 0; ma < 2; ma++) {
                    unsigned adr = stA + (unsigned)((wm + ma*16 + a_row)*SSTRIDE + kb + a_koff)*2u;
                    ldsm_x4(ah[ma], adr);
                    ldsm_x4(al[ma], adr + (unsigned)TILE_B);
                }
                #pragma unroll
                for (int g = 0; g < 2; g++) {
                    unsigned bdr = stA + (unsigned)(2*TILE_B)
                                 + (unsigned)((wn + g*16 + b_row)*SSTRIDE + kb + b_koff)*2u;
                    ldsm_x4(bh[g], bdr);
                    ldsm_x4(bl[g], bdr + (unsigned)TILE_B);
                }
                #pragma unroll
                for (int ma = 0; ma < 2; ma++)
                    #pragma unroll
                    for (int nb = 0; nb < 4; nb++)
                        mma16816(acc0[ma][nb], ah[ma], &bh[nb>>1][(nb&1)*2]);
                #pragma unroll
                for (int ma = 0; ma < 2; ma++)
                    #pragma unroll
                    for (int nb = 0; nb < 4; nb++)
                        mma16816(acc1[ma][nb], ah[ma], &bl[nb>>1][(nb&1)*2]);
                #pragma unroll
                for (int ma = 0; ma < 2; ma++)
                    #pragma unroll
                    for (int nb = 0; nb < 4; nb++)
                        mma16816(acc1[ma][nb], al[ma], &bh[nb>>1][(nb&1)*2]);
            }
        }
        int cc = c + NSTAGE - 1;
        if (cc < NKCHUNK) {
            unsigned sb = shs + (unsigned)((cc & (NSTAGE-1)) * STAGE_B) + dstOff;
            cp16(sb,            srcAh + cc*KC);
            cp16(sb + TILE_B,   srcAl + cc*KC);
            cp16(sb + 2*TILE_B, srcBh + cc*KC);
            cp16(sb + 3*TILE_B, srcBl + cc*KC);
            CP_COMMIT();
        }
    }
    __syncthreads();

    // ---- fused epilogue ----
    const float inv = 1.f / 2048.f;
    if (blockIdx.x == 0) {
        // match head: stage 128x128 fp32 tile, row norms, then fused matching
        float* ftile = (float*)sh;                    // [128][FSTRIDE]
        float* sred  = ftile + 128*FSTRIDE;           // [128][4]
        float* norms = sred + 128*4;                  // [128]
        #pragma unroll
        for (int ma = 0; ma < 2; ma++) {
            int r0 = wm + ma*16 + gid;
            #pragma unroll
            for (int nb = 0; nb < 4; nb++) {
                int c0 = wn + nb*8 + 2*t4;
                float cv0 = g_cvec[c0], cv1 = g_cvec[c0+1];
                ftile[r0*FSTRIDE + c0]       = acc0[ma][nb][0] + acc1[ma][nb][0]*inv + cv0;
                ftile[r0*FSTRIDE + c0 + 1]   = acc0[ma][nb][1] + acc1[ma][nb][1]*inv + cv1;
                ftile[(r0+8)*FSTRIDE + c0]   = acc0[ma][nb][2] + acc1[ma][nb][2]*inv + cv0;
                ftile[(r0+8)*FSTRIDE + c0+1] = acc0[ma][nb][3] + acc1[ma][nb][3]*inv + cv1;
            }
        }
        __syncthreads();
        int row = tid >> 2, seg = tid & 3;
        const float* fr = ftile + row*FSTRIDE + seg*32;
        float ss = 0.f;
        #pragma unroll
        for (int j = 0; j < 32; j++) { float v = fr[j]; ss += v*v; }
        sred[row*4 + seg] = ss;
        __syncthreads();
        if (seg == 0)
            norms[row] = sqrtf(sred[row*4+0] + sred[row*4+1] + sred[row*4+2] + sred[row*4+3]);
        __syncthreads();

        // ---- fused per-window sim + greedy matching (warps 0..7) ----
        if (warp < 8) {
            const int rb = warp * 16;                 // local window row base
            float sv[2];
            #pragma unroll
            for (int q = 0; q < 2; q++) {
                int f = lane + q*32;
                int a = f >> 3, c = f & 7;
                const float4* va = (const float4*)(ftile + (rb + 2*a) * FSTRIDE);
                const float4* vb = (const float4*)(ftile + (rb + 2*c + 1) * FSTRIDE);
                float acc = 0.f;
                #pragma unroll
                for (int d = 0; d < 32; d++) {
                    float4 u = va[d], v = vb[d];
                    acc += u.x*v.x + u.y*v.y + u.z*v.z + u.w*v.w;
                }
                acc = acc / (norms[rb + 2*a] * norms[rb + 2*c + 1]);
                sv[q] = (acc < -10.0f) ? -INFINITY : acc;
            }

            unsigned rowAvail = 0xFF, colAvail = 0xFF;
            int myA = 0, myC = 0; float myV = 0.f;
            #pragma unroll
            for (int r = 0; r < MAXP; r++) {
                float bestv = -INFINITY; int besti = 9999;
                #pragma unroll
                for (int q = 0; q < 2; q++) {
                    int f = lane + q*32;
                    int a = f >> 3, c = f & 7;
                    bool av = ((rowAvail >> a) & 1) && ((colAvail >> c) & 1);
                    float v = av ? sv[q] : -INFINITY;
                    int   idx = av ? f : 9999;
                    if (v > bestv || (v == bestv && idx < besti)) { bestv = v; besti = idx; }
                }
                #pragma unroll
                for (int o = 16; o; o >>= 1) {
                    float ov = __shfl_xor_sync(0xffffffffu, bestv, o);
                    int   oi = __shfl_xor_sync(0xffffffffu, besti, o);
                    if (ov > bestv || (ov == bestv && oi < besti)) { bestv = ov; besti = oi; }
                }
                int a = besti >> 3, c = besti & 7;
                rowAvail &= ~(1u << a);
                colAvail &= ~(1u << c);
                if (lane == r) { myA = a; myC = c; myV = bestv; }
            }

            if (lane < MAXP) {
                int tglob = bm + rb;                   // global token index of window start
                int b = tglob / TSEQ;
                int w = (tglob % TSEQ) / WIN;
                int p = b*PPAIR + w*MAXP + lane;
                g_pi[p] = w*WIN + 2*myA;
                g_pj[p] = w*WIN + 2*myC + 1;
                g_sv[p] = myV;
            }
        }
    } else {
        float sp[4] = {0.f, 0.f, 0.f, 0.f};
        #pragma unroll
        for (int ma = 0; ma < 2; ma++) {
            #pragma unroll
            for (int nb = 0; nb < 4; nb++) {
                int c0 = wn + nb*8 + 2*t4;
                float cv0 = g_cvec[bn + c0], cv1 = g_cvec[bn + c0 + 1];
                float w20 = w2[bn - MDIM + c0], w21 = w2[bn - MDIM + c0 + 1];
                float v00 = acc0[ma][nb][0] + acc1[ma][nb][0]*inv + cv0;
                float v01 = acc0[ma][nb][1] + acc1[ma][nb][1]*inv + cv1;
                float v10 = acc0[ma][nb][2] + acc1[ma][nb][2]*inv + cv0;
                float v11 = acc0[ma][nb][3] + acc1[ma][nb][3]*inv + cv1;
                sp[2*ma]   += fmaxf(v00, 0.f)*w20 + fmaxf(v01, 0.f)*w21;
                sp[2*ma+1] += fmaxf(v10, 0.f)*w20 + fmaxf(v11, 0.f)*w21;
            }
        }
        #pragma unroll
        for (int s = 0; s < 4; s++) {
            sp[s] += __shfl_xor_sync(0xffffffffu, sp[s], 1);
            sp[s] += __shfl_xor_sync(0xffffffffu, sp[s], 2);
        }
        float* red = (float*)sh;                      // [4 wn][128 rows]
        __syncthreads();
        if (t4 == 0) {
            int wncol = warp & 3;
            red[wncol*128 + wm + gid]          = sp[0];
            red[wncol*128 + wm + gid + 8]      = sp[1];
            red[wncol*128 + wm + 16 + gid]     = sp[2];
            red[wncol*128 + wm + 16 + gid + 8] = sp[3];
        }
        __syncthreads();
        if (tid < 128) {
            float p = red[tid] + red[128 + tid] + red[256 + tid] + red[384 + tid];
            g_impPart[(size_t)(blockIdx.x - 1)*NTOK + bm + tid] = p;
        }
    }
}

// ---------------- K3': pair scores from imp partials ------------------------
__global__ void score_kernel(const float* __restrict__ b2) {
    int p = blockIdx.x * 256 + threadIdx.x;          // 0..BSZ*PPAIR-1
    int b = p / PPAIR;
    int ti = b*TSEQ + g_pi[p];
    int tj = b*TSEQ + g_pj[p];
    float b2v = b2[0];
    float si = b2v + g_impPart[ti] + g_impPart[NTOK + ti] + g_impPart[2*NTOK + ti] + g_impPart[3*NTOK + ti];
    float sj = b2v + g_impPart[tj] + g_impPart[NTOK + tj] + g_impPart[2*NTOK + tj] + g_impPart[3*NTOK + tj];
    float ii = 1.f / (1.f + expf(-si));
    float ij = 1.f / (1.f + expf(-sj));
    g_ps[p]  = g_sv[p] - 0.25f * (ii + ij);
    g_pal[p] = 1.f / (1.f + expf(-5.f * (ii - ij)));
}

// ---------------- K4: per-batch top-K, scatter, shfl-scan, inverse map ------
__global__ void select_pack_kernel() {
    int b = blockIdx.x;
    int tid = threadIdx.x;
    int lane = tid & 31, wrp = tid >> 5;
    __shared__ float svv[1024];
    __shared__ int   sii[1024];
    __shared__ int   sdrop[TSEQ];
    __shared__ int   wsum[32];

    svv[tid] = (tid < PPAIR) ? g_ps[b*PPAIR + tid] : -INFINITY;
    sii[tid] = tid;
    __syncthreads();

    for (int ksz = 2; ksz <= 1024; ksz <<= 1) {
        for (int jsz = ksz >> 1; jsz > 0; jsz >>= 1) {
            int ixj = tid ^ jsz;
            if (ixj > tid) {
                float v1 = svv[tid], v2 = svv[ixj];
                int   i1 = sii[tid], i2 = sii[ixj];
                bool tid_before = (v1 > v2) || (v1 == v2 && i1 < i2);
                bool doswap = ((tid & ksz) == 0) ? !tid_before : tid_before;
                if (doswap) { svv[tid]=v2; svv[ixj]=v1; sii[tid]=i2; sii[ixj]=i1; }
            }
            __syncthreads();
        }
    }

    for (int t = tid; t < TSEQ; t += 1024) { sdrop[t] = 0; g_partner[b*TSEQ + t] = -1; }
    __syncthreads();

    if (tid < KSEL) {
        int p = sii[tid];
        int i = g_pi[b*PPAIR + p];
        int j = g_pj[b*PPAIR + p];
        sdrop[j] = 1;
        g_partner[b*TSEQ + i] = j;
        g_atok[b*TSEQ + i] = g_pal[b*PPAIR + p];
    }
    __syncthreads();

    int k0 = 1 - sdrop[2*tid];
    int k1 = 1 - sdrop[2*tid + 1];
    int mysum = k0 + k1;

    int v = mysum;
    #pragma unroll
    for (int o = 1; o < 32; o <<= 1) {
        int n = __shfl_up_sync(0xffffffffu, v, o);
        if (lane >= o) v += n;
    }
    if (lane == 31) wsum[wrp] = v;
    __syncthreads();
    if (wrp == 0) {
        int wv = wsum[lane];
        #pragma unroll
        for (int o = 1; o < 32; o <<= 1) {
            int n = __shfl_up_sync(0xffffffffu, wv, o);
            if (lane >= o) wv += n;
        }
        wsum[lane] = wv;
    }
    __syncthreads();
    int incl = v + (wrp ? wsum[wrp - 1] : 0);
    int excl = incl - mysum;
    if (k0) g_inv[b*TKEEP + excl]      = 2*tid;
    if (k1) g_inv[b*TKEEP + excl + k0] = 2*tid + 1;
}

// ---------------- K5: merge + compact output (output-row indexed) -----------
__global__ void pack_out_kernel(const float* __restrict__ x, float* __restrict__ out) {
    int r = blockIdx.x, b = blockIdx.y;
    int t = g_inv[b*TKEEP + r];
    int bt = b*TSEQ + t;
    const float4* xi = (const float4*)(x + (size_t)bt * DIM);
    float4* o = (float4*)(out + ((size_t)b*TKEEP + r) * DIM);
    int pj = g_partner[bt];
    if (pj < 0) {
        for (int i = threadIdx.x; i < DIM/4; i += blockDim.x) o[i] = xi[i];
    } else {
        float a  = g_atok[bt];
        float ai = a, aj = 1.f - a;
        const float4* xj = (const float4*)(x + ((size_t)b*TSEQ + pj) * DIM);
        for (int i = threadIdx.x; i < DIM/4; i += blockDim.x) {
            float4 u = xi[i], v = xj[i], m, w;
            m.x = ai*u.x + aj*v.x;  m.y = ai*u.y + aj*v.y;
            m.z = ai*u.z + aj*v.z;  m.w = ai*u.w + aj*v.w;
            w.x = u.x + (m.x - u.x); w.y = u.y + (m.y - u.y);
            w.z = u.z + (m.z - u.z); w.w = u.w + (m.w - u.w);
            o[i] = w;
        }
    }
}

// ---------------- launch ----------------------------------------------------
extern "C" void kernel_launch(void* const* d_in, const int* in_sizes, int n_in,
                              void* d_out, int out_size) {
    const float* x    = (const float*)d_in[0];
    const float* gm   = (const float*)d_in[1];
    const float* bm   = (const float*)d_in[2];
    const float* wm   = (const float*)d_in[3];
    const float* gi   = (const float*)d_in[4];
    const float* bi   = (const float*)d_in[5];
    const float* w1   = (const float*)d_in[6];
    const float* b1   = (const float*)d_in[7];
    const float* w2   = (const float*)d_in[8];
    const float* b2   = (const float*)d_in[9];
    float* out = (float*)d_out;

    cudaFuncSetAttribute(gemm_hmma_kernel, cudaFuncAttributeMaxDynamicSharedMemorySize, GEMM_SMEM);

    ln_split_kernel<<<NTOK/8, 256>>>(x);
    foldW_kernel<<<dim3(DIM/32, NCOL/32), dim3(32, 8)>>>(wm, w1, gm, gi);
    foldC_kernel<<<NCOL, 256>>>(wm, w1, bm, bi, b1);
    gemm_hmma_kernel<<<dim3(NCOL/128, NTOK/128), 512, GEMM_SMEM>>>(w2);
    score_kernel<<<(BSZ*PPAIR)/256, 256>>>(b2);
    select_pack_kernel<<<BSZ, 1024>>>();
    pack_out_kernel<<<dim3(TKEEP, BSZ), 128>>>(x, out);
}